// round 1
// baseline (speedup 1.0000x reference)
#include <cuda_runtime.h>
#include <cstdint>

#define DI      8192
#define DO      8192
#define NBATCH  1024
#define FAN     16
#define NNZ     (DI * FAN)          // 131072
#define BT      4                   // batch rows per CTA (float4 lanes)
#define NBT     (NBATCH / BT)       // 256
#define JSPLIT  2
#define JPER    (DO / JSPLIT)       // 4096
#define THREADS 512
#define SMEM_BYTES (DI * 16)        // 8192 float4 = 128 KB

// Scratch (no allocation allowed): CSR-style fixed-degree index table.
// g_idx[j*16 + s] = swizzled pre-index of the s-th edge into output j.
__device__ __align__(16) unsigned short g_idx[DO * FAN];
__device__ int g_cnt[DO];

__device__ __forceinline__ unsigned swz(unsigned i) {
    // XOR swizzle on float4 index: makes the transpose-store phase conflict-free.
    return i ^ ((i >> 3) & 7u);
}

__global__ void zero_cnt_kernel() {
    int i = blockIdx.x * blockDim.x + threadIdx.x;
    if (i < DO) g_cnt[i] = 0;
}

__global__ void build_kernel(const int* __restrict__ pre,
                             const int* __restrict__ post) {
    int e = blockIdx.x * blockDim.x + threadIdx.x;
    if (e < NNZ) {
        int j = post[e];
        int s = atomicAdd(&g_cnt[j], 1);
        if (s < FAN) {
            unsigned i = (unsigned)pre[e];
            g_idx[j * FAN + s] = (unsigned short)swz(i);
        }
    }
}

__global__ void __launch_bounds__(THREADS, 1)
gather_kernel(const float* __restrict__ x, float* __restrict__ y) {
    extern __shared__ float4 xs[];   // xs[swz(i)] = {x[b0][i], x[b1][i], x[b2][i], x[b3][i]}

    const int b0    = blockIdx.y * BT;
    const int jbase = blockIdx.x * JPER;

    // ---- Stage + transpose 4 batch rows into SMEM (swizzled, conflict-free STS.128) ----
    const float4* r0 = reinterpret_cast<const float4*>(x + (size_t)(b0 + 0) * DI);
    const float4* r1 = reinterpret_cast<const float4*>(x + (size_t)(b0 + 1) * DI);
    const float4* r2 = reinterpret_cast<const float4*>(x + (size_t)(b0 + 2) * DI);
    const float4* r3 = reinterpret_cast<const float4*>(x + (size_t)(b0 + 3) * DI);

    for (int t = threadIdx.x; t < DI / 4; t += THREADS) {
        float4 v0 = r0[t], v1 = r1[t], v2 = r2[t], v3 = r3[t];
        unsigned i = (unsigned)t * 4u;
        xs[swz(i + 0)] = make_float4(v0.x, v1.x, v2.x, v3.x);
        xs[swz(i + 1)] = make_float4(v0.y, v1.y, v2.y, v3.y);
        xs[swz(i + 2)] = make_float4(v0.z, v1.z, v2.z, v3.z);
        xs[swz(i + 3)] = make_float4(v0.w, v1.w, v2.w, v3.w);
    }
    __syncthreads();

    unsigned xs_base;
    asm("{ .reg .u64 t; cvta.to.shared.u64 t, %1; cvt.u32.u64 %0, t; }"
        : "=r"(xs_base) : "l"(xs));

    const uint4* idx4 = reinterpret_cast<const uint4*>(g_idx);  // 2 uint4 per j (16 x u16)

    const int NIT = JPER / THREADS;   // 8
    int j = jbase + threadIdx.x;
    uint4 A = idx4[2 * j];
    uint4 B = idx4[2 * j + 1];

    for (int it = 0; it < NIT; ++it) {
        // prefetch next iteration's indices (hide L2 latency)
        int jn = j + THREADS;
        uint4 An = A, Bn = B;
        if (it + 1 < NIT) { An = idx4[2 * jn]; Bn = idx4[2 * jn + 1]; }

        unsigned long long acc01 = 0ull, acc23 = 0ull;   // packed (b0,b1),(b2,b3)
        unsigned words[8] = {A.x, A.y, A.z, A.w, B.x, B.y, B.z, B.w};

        #pragma unroll
        for (int w = 0; w < 8; ++w) {
            unsigned v  = words[w];
            unsigned a0 = xs_base + (v & 0xFFFFu) * 16u;
            unsigned a1 = xs_base + (v >> 16)     * 16u;

            unsigned long long p01, p23, q01, q23;
            asm volatile(
                "{\n\t.reg .b32 a,b,c,d;\n\t"
                "ld.shared.v4.b32 {a,b,c,d},[%2];\n\t"
                "mov.b64 %0,{a,b};\n\t"
                "mov.b64 %1,{c,d};\n\t}"
                : "=l"(p01), "=l"(p23) : "r"(a0));
            asm volatile(
                "{\n\t.reg .b32 a,b,c,d;\n\t"
                "ld.shared.v4.b32 {a,b,c,d},[%2];\n\t"
                "mov.b64 %0,{a,b};\n\t"
                "mov.b64 %1,{c,d};\n\t}"
                : "=l"(q01), "=l"(q23) : "r"(a1));

            // packed fp32 adds — ptxas will not fuse these from C++
            asm("add.rn.f32x2 %0,%0,%1;" : "+l"(acc01) : "l"(p01));
            asm("add.rn.f32x2 %0,%0,%1;" : "+l"(acc23) : "l"(p23));
            asm("add.rn.f32x2 %0,%0,%1;" : "+l"(acc01) : "l"(q01));
            asm("add.rn.f32x2 %0,%0,%1;" : "+l"(acc23) : "l"(q23));
        }

        float f0, f1, f2, f3;
        asm("mov.b64 {%0,%1},%2;" : "=f"(f0), "=f"(f1) : "l"(acc01));
        asm("mov.b64 {%0,%1},%2;" : "=f"(f2), "=f"(f3) : "l"(acc23));

        y[(size_t)(b0 + 0) * DO + j] = 100.0f * f0;
        y[(size_t)(b0 + 1) * DO + j] = 100.0f * f1;
        y[(size_t)(b0 + 2) * DO + j] = 100.0f * f2;
        y[(size_t)(b0 + 3) * DO + j] = 100.0f * f3;

        j = jn; A = An; B = Bn;
    }
}

extern "C" void kernel_launch(void* const* d_in, const int* in_sizes, int n_in,
                              void* d_out, int out_size) {
    const float* x    = (const float*)d_in[0];
    const int*   pre  = (const int*)d_in[1];
    const int*   post = (const int*)d_in[2];
    float*       y    = (float*)d_out;

    (void)in_sizes; (void)n_in; (void)out_size;

    cudaFuncSetAttribute(gather_kernel,
                         cudaFuncAttributeMaxDynamicSharedMemorySize, SMEM_BYTES);

    zero_cnt_kernel<<<DO / 256, 256>>>();
    build_kernel<<<NNZ / 256, 256>>>(pre, post);
    gather_kernel<<<dim3(JSPLIT, NBT), THREADS, SMEM_BYTES>>>(x, y);
}

// round 2
// speedup vs baseline: 1.1776x; 1.1776x over previous
#include <cuda_runtime.h>
#include <cstdint>

#define DI      8192
#define DO      8192
#define NB      1024
#define FAN     16
#define NNZ     (DI * FAN)          // 131072
#define BT      4                   // batch rows per CTA tile (float4 lanes)
#define NBT     (NB / BT)           // 256 batch tiles
#define JCHUNK  1024                // j's per fine work unit
#define NJC     (DO / JCHUNK)       // 8 j-chunks per btile
#define UNITS   (NBT * NJC)         // 2048 fine units
#define THREADS 512
#define SMEM_BYTES (DI * 16)        // 8192 float4 = 128 KB

// Scratch (no allocation allowed): fixed-degree index table.
// g_idx[j*16 + s] = swizzled pre-index (float4 slot) of the s-th edge into j.
__device__ __align__(16) unsigned short g_idx[DO * FAN];
// Modular slot counter: each launch adds exactly FAN per j, so
// (atomicAdd & 15) enumerates slots 0..15 uniquely per launch — NO reset pass.
__device__ unsigned g_cnt[DO];

__device__ __forceinline__ unsigned swz(unsigned i) {
    // XOR swizzle on float4 index: makes the transpose-store phase conflict-free.
    return i ^ ((i >> 3) & 7u);
}

__global__ void build_kernel(const int* __restrict__ pre,
                             const int* __restrict__ post) {
    int e0 = (blockIdx.x * blockDim.x + threadIdx.x) * 4;
    int4 jj = *reinterpret_cast<const int4*>(post + e0);
    int4 ii = *reinterpret_cast<const int4*>(pre + e0);
    int j[4] = {jj.x, jj.y, jj.z, jj.w};
    int i[4] = {ii.x, ii.y, ii.z, ii.w};
    #pragma unroll
    for (int k = 0; k < 4; ++k) {
        unsigned s = atomicAdd(&g_cnt[j[k]], 1u) & 15u;
        g_idx[j[k] * FAN + s] = (unsigned short)swz((unsigned)i[k]);
    }
}

__global__ void __launch_bounds__(THREADS, 1)
gather_kernel(const float* __restrict__ x, float* __restrict__ y, int ncta) {
    extern __shared__ float4 xs[];   // xs[swz(i)] = 100*{x[b0][i],...,x[b3][i]}

    unsigned xs_base;
    asm("{ .reg .u64 t; cvta.to.shared.u64 t, %1; cvt.u32.u64 %0, t; }"
        : "=r"(xs_base) : "l"(xs));

    const uint4* idx4 = reinterpret_cast<const uint4*>(g_idx);

    // Contiguous static range of fine units for this CTA (balanced to 1 unit).
    int u0 = (int)(((long long)blockIdx.x       * UNITS) / ncta);
    int u1 = (int)(((long long)(blockIdx.x + 1) * UNITS) / ncta);

    int curb = -1;
    for (int u = u0; u < u1; ++u) {
        int b  = u >> 3;         // NJC = 8
        int jc = u & 7;
        int b0 = b * BT;

        if (b != curb) {
            if (curb >= 0) __syncthreads();   // everyone done with old tile
            // ---- Stage + transpose 4 batch rows (scaled by 100), swizzled ----
            const float4* r0 = reinterpret_cast<const float4*>(x + (size_t)(b0 + 0) * DI);
            const float4* r1 = reinterpret_cast<const float4*>(x + (size_t)(b0 + 1) * DI);
            const float4* r2 = reinterpret_cast<const float4*>(x + (size_t)(b0 + 2) * DI);
            const float4* r3 = reinterpret_cast<const float4*>(x + (size_t)(b0 + 3) * DI);
            #pragma unroll
            for (int t = threadIdx.x; t < DI / 4; t += THREADS) {
                float4 v0 = r0[t], v1 = r1[t], v2 = r2[t], v3 = r3[t];
                unsigned i = (unsigned)t * 4u;
                xs[swz(i + 0)] = make_float4(100.f*v0.x, 100.f*v1.x, 100.f*v2.x, 100.f*v3.x);
                xs[swz(i + 1)] = make_float4(100.f*v0.y, 100.f*v1.y, 100.f*v2.y, 100.f*v3.y);
                xs[swz(i + 2)] = make_float4(100.f*v0.z, 100.f*v1.z, 100.f*v2.z, 100.f*v3.z);
                xs[swz(i + 3)] = make_float4(100.f*v0.w, 100.f*v1.w, 100.f*v2.w, 100.f*v3.w);
            }
            __syncthreads();
            curb = b;
        }

        // ---- Gather: 2 j's per thread in this unit ----
        #pragma unroll
        for (int h = 0; h < 2; ++h) {
            int j = jc * JCHUNK + h * THREADS + threadIdx.x;
            uint4 A = idx4[2 * j];
            uint4 B = idx4[2 * j + 1];

            unsigned long long acc01 = 0ull, acc23 = 0ull;  // packed (b0,b1),(b2,b3)
            unsigned words[8] = {A.x, A.y, A.z, A.w, B.x, B.y, B.z, B.w};

            #pragma unroll
            for (int w = 0; w < 8; ++w) {
                unsigned v  = words[w];
                unsigned a0 = xs_base + (v & 0xFFFFu) * 16u;
                unsigned a1 = xs_base + (v >> 16)     * 16u;

                unsigned long long p01, p23, q01, q23;
                asm volatile(
                    "{\n\t.reg .b32 a,b,c,d;\n\t"
                    "ld.shared.v4.b32 {a,b,c,d},[%2];\n\t"
                    "mov.b64 %0,{a,b};\n\t"
                    "mov.b64 %1,{c,d};\n\t}"
                    : "=l"(p01), "=l"(p23) : "r"(a0));
                asm volatile(
                    "{\n\t.reg .b32 a,b,c,d;\n\t"
                    "ld.shared.v4.b32 {a,b,c,d},[%2];\n\t"
                    "mov.b64 %0,{a,b};\n\t"
                    "mov.b64 %1,{c,d};\n\t}"
                    : "=l"(q01), "=l"(q23) : "r"(a1));

                // packed fp32 adds — ptxas never fuses these from C++
                asm("add.rn.f32x2 %0,%0,%1;" : "+l"(acc01) : "l"(p01));
                asm("add.rn.f32x2 %0,%0,%1;" : "+l"(acc23) : "l"(p23));
                asm("add.rn.f32x2 %0,%0,%1;" : "+l"(acc01) : "l"(q01));
                asm("add.rn.f32x2 %0,%0,%1;" : "+l"(acc23) : "l"(q23));
            }

            float f0, f1, f2, f3;
            asm("mov.b64 {%0,%1},%2;" : "=f"(f0), "=f"(f1) : "l"(acc01));
            asm("mov.b64 {%0,%1},%2;" : "=f"(f2), "=f"(f3) : "l"(acc23));

            y[(size_t)(b0 + 0) * DO + j] = f0;
            y[(size_t)(b0 + 1) * DO + j] = f1;
            y[(size_t)(b0 + 2) * DO + j] = f2;
            y[(size_t)(b0 + 3) * DO + j] = f3;
        }
    }
}

extern "C" void kernel_launch(void* const* d_in, const int* in_sizes, int n_in,
                              void* d_out, int out_size) {
    const float* x    = (const float*)d_in[0];
    const int*   pre  = (const int*)d_in[1];
    const int*   post = (const int*)d_in[2];
    float*       y    = (float*)d_out;

    (void)in_sizes; (void)n_in; (void)out_size;

    // Host code runs only during capture; attribute query is not a stream op.
    int nsm = 0;
    cudaDeviceGetAttribute(&nsm, cudaDevAttrMultiProcessorCount, 0);
    if (nsm <= 0) nsm = 148;

    cudaFuncSetAttribute(gather_kernel,
                         cudaFuncAttributeMaxDynamicSharedMemorySize, SMEM_BYTES);

    build_kernel<<<NNZ / (256 * 4), 256>>>(pre, post);
    gather_kernel<<<nsm, THREADS, SMEM_BYTES>>>(x, y, nsm);
}